// round 14
// baseline (speedup 1.0000x reference)
#include <cuda_runtime.h>

#define BN 8
#define JN 64
#define CN 32
#define CG 8               // channels per block group (grid.z = CN/CG = 4)
#define HT 8
#define HIMG_ 256
#define WIMG_ 256
#define HW (HIMG_*WIMG_)

// mask_mode: 0 = float mask after res, 1 = uint8 mask packed after res, 2 = no mask
__global__ void __launch_bounds__(256, 5)
roirotate_kernel(const float* __restrict__ image,
                 const float* __restrict__ boxes,
                 float* __restrict__ out,
                 int max_w, float inv_w, int mask_mode)
{
    const int bj = blockIdx.y;               // 0 .. B*J-1
    const int b  = bj >> 6;                  // JN = 64
    const int c0 = blockIdx.z * CG;

    const float* bx = boxes + bj * 5;
    float l   = bx[0];
    float t   = bx[1];
    float r   = bx[2];
    float btm = bx[3];

    float bw = r - l;
    float bh = btm - t;
    // widths = int32( (bw/bh) * 8 ) in float32 arithmetic — keep EXACT
    int width = (int)(__fmul_rn(__fdiv_rn(bw, bh), 8.0f));
    float each_w = bw / (float)(width - 1);
    float each_h = bh * (1.0f / 7.0f);        // HEIGHT-1 = 7

    const int chw = HT * max_w;               // per-channel output stride (even)
    const float* imgb = image + (b * CN + c0) * HW;
    float* outb = out + (bj * CN + c0) * chw;

    // ---- mask (only one slice of blocks writes it) ----
    if (blockIdx.x == 0 && blockIdx.z == 0) {
        if (mask_mode == 0) {
            float* maskp = out + BN * JN * CN * chw + bj * max_w;
            for (int k = threadIdx.x; k < max_w; k += blockDim.x)
                maskp[k] = (k < width) ? 1.0f : 0.0f;
        } else if (mask_mode == 1) {
            unsigned char* maskp =
                (unsigned char*)(out + BN * JN * CN * chw) + bj * max_w;
            for (int k = threadIdx.x; k < max_w; k += blockDim.x)
                maskp[k] = (k < width) ? (unsigned char)1 : (unsigned char)0;
        }
    }

    // Each thread owns two consecutive elements idx0 (even) and idx0+1.
    const int idx0 = (blockIdx.x * blockDim.x + threadIdx.x) * 2;
    if (idx0 >= chw) return;                  // chw even -> idx0+1 also valid

    // i = idx0 / max_w, k = idx0 % max_w via float reciprocal + exact fixup
    int i0 = (int)((float)idx0 * inv_w);
    int k0 = idx0 - i0 * max_w;
    if (k0 < 0)           { i0--; k0 += max_w; }
    else if (k0 >= max_w) { i0++; k0 -= max_w; }
    int i1 = i0, k1 = k0 + 1;
    if (k1 == max_w) { k1 = 0; i1++; }

    const bool live0 = (k0 < width);
    const bool live1 = (k1 < width);

    float* op = outb + idx0;                  // 8B-aligned (idx0 even, outb even)

    if (!live0 && !live1) {
        // both masked -> zero pair per channel
        const float2 z2 = make_float2(0.f, 0.f);
        float* o = op;
        #pragma unroll
        for (int c = 0; c < CG; c++) { *(float2*)o = z2; o += chw; }
        return;
    }

    // ---- weights & offsets for both elements ----
    float wa0, wb0, wc0, wd0; int o00_0, o01_0, o10_0, o11_0;
    float wa1, wb1, wc1, wd1; int o00_1, o01_1, o10_1, o11_1;

    {
        float x = (float)k0 * each_w + l;
        float y = (float)i0 * each_h + t;
        float fx = floorf(x), fy = floorf(y);
        int x0 = min(max((int)fx,     0), WIMG_ - 1);
        int x1 = min(max((int)fx + 1, 0), WIMG_ - 1);
        int y0 = min(max((int)fy,     0), HIMG_ - 1);
        int y1 = min(max((int)fy + 1, 0), HIMG_ - 1);
        float wx0 = x - (float)x0, wx1 = (float)x1 - x;
        float wy0 = y - (float)y0, wy1 = (float)y1 - y;
        wa0 = wx1 * wy1; wb0 = wx1 * wy0; wc0 = wx0 * wy1; wd0 = wx0 * wy0;
        o00_0 = y0 * WIMG_ + x0; o01_0 = y0 * WIMG_ + x1;
        o10_0 = y1 * WIMG_ + x0; o11_0 = y1 * WIMG_ + x1;
    }
    {
        float x = (float)k1 * each_w + l;
        float y = (float)i1 * each_h + t;
        float fx = floorf(x), fy = floorf(y);
        int x0 = min(max((int)fx,     0), WIMG_ - 1);
        int x1 = min(max((int)fx + 1, 0), WIMG_ - 1);
        int y0 = min(max((int)fy,     0), HIMG_ - 1);
        int y1 = min(max((int)fy + 1, 0), HIMG_ - 1);
        float wx0 = x - (float)x0, wx1 = (float)x1 - x;
        float wy0 = y - (float)y0, wy1 = (float)y1 - y;
        wa1 = wx1 * wy1; wb1 = wx1 * wy0; wc1 = wx0 * wy1; wd1 = wx0 * wy0;
        o00_1 = y0 * WIMG_ + x0; o01_1 = y0 * WIMG_ + x1;
        o10_1 = y1 * WIMG_ + x0; o11_1 = y1 * WIMG_ + x1;
    }

    const float* ip = imgb;
    float* o = op;
    #pragma unroll
    for (int c = 0; c < CG; c++) {
        float v0 = 0.0f, v1 = 0.0f;
        if (live0) {
            v0 = __ldg(ip + o00_0) * wa0
               + __ldg(ip + o10_0) * wb0
               + __ldg(ip + o01_0) * wc0
               + __ldg(ip + o11_0) * wd0;
        }
        if (live1) {
            v1 = __ldg(ip + o00_1) * wa1
               + __ldg(ip + o10_1) * wb1
               + __ldg(ip + o01_1) * wc1
               + __ldg(ip + o11_1) * wd1;
        }
        *(float2*)o = make_float2(v0, v1);
        ip += HW;
        o  += chw;
    }
}

extern "C" void kernel_launch(void* const* d_in, const int* in_sizes, int n_in,
                              void* d_out, int out_size)
{
    const float* image = (const float*)d_in[0];
    const float* boxes = (const float*)d_in[1];
    float* out = (float*)d_out;

    // Derive max_w from out_size (host-side, no sync needed).
    const long long per_res = (long long)BN * JN * CN * HT;     // 131072
    const long long per_fmask = per_res + (long long)BN * JN;   // 131584 (float mask)
    const long long per_u8 = per_res + (long long)BN * JN / 4;  // 131200 (u8 mask)

    int max_w, mask_mode;
    long long osz = (long long)out_size;
    if (osz % per_fmask == 0) {
        max_w = (int)(osz / per_fmask);
        mask_mode = 0;
    } else if (osz % per_u8 == 0) {
        max_w = (int)(osz / per_u8);
        mask_mode = 1;
    } else if (osz % per_res == 0) {
        max_w = (int)(osz / per_res);
        mask_mode = 2;
    } else {
        max_w = (int)(osz / per_fmask);
        mask_mode = 0;
    }

    const int block = 256;
    int pairs = HT * max_w / 2;                       // chw even
    int slices = (pairs + block - 1) / block;
    dim3 grid(slices, BN * JN, CN / CG);
    float inv_w = 1.0f / (float)max_w;
    roirotate_kernel<<<grid, block>>>(image, boxes, out, max_w, inv_w, mask_mode);
}